// round 6
// baseline (speedup 1.0000x reference)
#include <cuda_runtime.h>
#include <math.h>

#define NB   4
#define NTOK 2304
#define DIM  256
#define AGH  512

// ---------------- scratch (device globals; no allocation allowed) ----------------
__device__ float g_Xall[NB*NTOK*512];          // [b][n][c] c=0..255 ir, 256..511 vis
__device__ float g_h1[NB*NTOK*AGH];
__device__ float g_lf[NB*NTOK];
__device__ float g_maskf[NB*NTOK];
__device__ int   g_idx[NB*NTOK];
__device__ int   g_S[NB];
__device__ float g_X[2*NB*NTOK*DIM];           // compacted tokens, slot = mod*NB+b
__device__ float g_xn[2*NB*NTOK*DIM];
__device__ float g_qkv[2*NB*NTOK*3*DIM];
__device__ float g_attn[2*NB*NTOK*DIM];
__device__ float g_x1[2*NB*NTOK*DIM];
__device__ float g_hff[2*NB*NTOK*4*DIM];
__device__ float g_mix[2*NB*NTOK*DIM];

// ---------------- tf32 helpers --------------------------------------------------
__device__ __forceinline__ unsigned f2tf(float x) {
    unsigned u; asm("cvt.rna.tf32.f32 %0, %1;" : "=r"(u) : "f"(x)); return u;
}
__device__ __forceinline__ void mma8(float (&c)[4], const unsigned (&a)[4],
                                     const unsigned (&b)[2]) {
    asm volatile(
        "mma.sync.aligned.m16n8k8.row.col.f32.tf32.tf32.f32 "
        "{%0,%1,%2,%3}, {%4,%5,%6,%7}, {%8,%9}, {%0,%1,%2,%3};"
        : "+f"(c[0]), "+f"(c[1]), "+f"(c[2]), "+f"(c[3])
        : "r"(a[0]), "r"(a[1]), "r"(a[2]), "r"(a[3]), "r"(b[0]), "r"(b[1]));
}

// ---------------- prep: transpose to token-major concat + base canvas -----------
__global__ void prep_kernel(const float* __restrict__ f_ir,
                            const float* __restrict__ f_vis,
                            float* __restrict__ out)
{
    __shared__ float ti[32][33], tv[32][33];
    int b = blockIdx.z;
    int c0 = blockIdx.y * 32;
    int n0 = blockIdx.x * 32;
#pragma unroll
    for (int i = 0; i < 4; i++) {
        int c = c0 + threadIdx.y + i * 8;
        size_t off = ((size_t)b*256 + c)*NTOK + n0 + threadIdx.x;
        float vi = f_ir[off], vv = f_vis[off];
        ti[threadIdx.y + i*8][threadIdx.x] = vi;
        tv[threadIdx.y + i*8][threadIdx.x] = vv;
        out[off] = vi + vv;
    }
    __syncthreads();
#pragma unroll
    for (int i = 0; i < 4; i++) {
        int n = n0 + threadIdx.y + i * 8;
        size_t base = ((size_t)b*NTOK + n)*512;
        g_Xall[base + c0 + threadIdx.x]       = ti[threadIdx.x][threadIdx.y + i*8];
        g_Xall[base + 256 + c0 + threadIdx.x] = tv[threadIdx.x][threadIdx.y + i*8];
    }
}

// ---------------- generic tf32 tensor-core GEMM, register-staged pipeline -------
// block tile 128(M) x 64(N), K-chunk 32, 8 warps (4 M x 2 N), warp tile 32x32.
// Pipeline: stage(cvt+STS) chunk k -> sync -> issue LDG for k+1 -> mma chunk k.
// HILO: 3xTF32 fp32-grade accuracy (agent path — logits sit near zero).
template<int ACT, bool RES, bool USE_S, bool HILO>
__global__ void tgemm(const float* __restrict__ A,
                      const float* __restrict__ W0, const float* __restrict__ W1,
                      const float* __restrict__ bias0, const float* __restrict__ bias1,
                      const float* __restrict__ R, float* __restrict__ C,
                      int K, int N)
{
    int z = blockIdx.z;
    int b = z & (NB - 1);
    int S = USE_S ? g_S[b] : NTOK;
    int row0 = blockIdx.x * 128;
    if (row0 >= S) return;
    const float* W    = (z < NB) ? W0 : W1;
    const float* bias = (z < NB) ? bias0 : bias1;
    int n0 = blockIdx.y * 64;
    const float* Ab = A + (size_t)z * NTOK * K;
    float*       Cb = C + (size_t)z * NTOK * N;
    const float* Rb = RES ? (R + (size_t)z * NTOK * N) : nullptr;

    extern __shared__ unsigned sh[];
    unsigned* As_hi = sh;                   // 128*36
    unsigned* Ws_hi = sh + 128*36;          // 64*36
    unsigned* As_lo = HILO ? sh + 192*36 : nullptr;
    unsigned* Ws_lo = HILO ? sh + 320*36 : nullptr;

    int tid  = threadIdx.x;
    int warp = tid >> 5, lane = tid & 31;
    int g = lane >> 2, tig = lane & 3;
    int wm = warp >> 1, wn = warp & 1;

    // per-thread staging coordinates (fixed across chunks)
    int ar = tid >> 3;                   // A rows: tid/8 + it*32
    int ac4 = (tid & 7) * 4;             // A col group
    int wr = tid >> 3;                   // W rows: tid/8 + it*32 (2 its)
    int wc4 = (tid & 7) * 4;

    float acc[2][4][4];
#pragma unroll
    for (int mi = 0; mi < 2; mi++)
#pragma unroll
        for (int ni = 0; ni < 4; ni++)
#pragma unroll
            for (int q = 0; q < 4; q++) acc[mi][ni][q] = 0.f;

    float4 av[4], wv[2];
    // prologue: load chunk 0 into registers
#pragma unroll
    for (int it = 0; it < 4; it++) {
        int row = row0 + ar + it * 32;
        av[it] = make_float4(0.f, 0.f, 0.f, 0.f);
        if (row < S) av[it] = *(const float4*)&Ab[(size_t)row * K + ac4];
    }
#pragma unroll
    for (int it = 0; it < 2; it++) {
        wv[it] = *(const float4*)&W[(size_t)(n0 + wr + it * 32) * K + wc4];
    }

    for (int k0 = 0; k0 < K; k0 += 32) {
        // stage current chunk: cvt + STS
#pragma unroll
        for (int it = 0; it < 4; it++) {
            int r = ar + it * 32;
            uint4 hv;
            hv.x = f2tf(av[it].x); hv.y = f2tf(av[it].y);
            hv.z = f2tf(av[it].z); hv.w = f2tf(av[it].w);
            *(uint4*)&As_hi[r*36 + ac4] = hv;
            if (HILO) {
                uint4 lv;
                lv.x = f2tf(av[it].x - __uint_as_float(hv.x));
                lv.y = f2tf(av[it].y - __uint_as_float(hv.y));
                lv.z = f2tf(av[it].z - __uint_as_float(hv.z));
                lv.w = f2tf(av[it].w - __uint_as_float(hv.w));
                *(uint4*)&As_lo[r*36 + ac4] = lv;
            }
        }
#pragma unroll
        for (int it = 0; it < 2; it++) {
            int r = wr + it * 32;
            uint4 hv;
            hv.x = f2tf(wv[it].x); hv.y = f2tf(wv[it].y);
            hv.z = f2tf(wv[it].z); hv.w = f2tf(wv[it].w);
            *(uint4*)&Ws_hi[r*36 + wc4] = hv;
            if (HILO) {
                uint4 lv;
                lv.x = f2tf(wv[it].x - __uint_as_float(hv.x));
                lv.y = f2tf(wv[it].y - __uint_as_float(hv.y));
                lv.z = f2tf(wv[it].z - __uint_as_float(hv.z));
                lv.w = f2tf(wv[it].w - __uint_as_float(hv.w));
                *(uint4*)&Ws_lo[r*36 + wc4] = lv;
            }
        }
        __syncthreads();

        // prefetch next chunk into registers (overlaps with mma below)
        int kn = k0 + 32;
        if (kn < K) {
#pragma unroll
            for (int it = 0; it < 4; it++) {
                int row = row0 + ar + it * 32;
                av[it] = make_float4(0.f, 0.f, 0.f, 0.f);
                if (row < S) av[it] = *(const float4*)&Ab[(size_t)row * K + kn + ac4];
            }
#pragma unroll
            for (int it = 0; it < 2; it++) {
                wv[it] = *(const float4*)&W[(size_t)(n0 + wr + it * 32) * K + kn + wc4];
            }
        }

#pragma unroll
        for (int ks = 0; ks < 4; ks++) {
            int base = ks * 8;
            unsigned a_hi[2][4], b_hi[4][2];
#pragma unroll
            for (int mi = 0; mi < 2; mi++) {
                int rb = wm*32 + mi*16;
                a_hi[mi][0] = As_hi[(rb + g    )*36 + base + tig];
                a_hi[mi][1] = As_hi[(rb + 8 + g)*36 + base + tig];
                a_hi[mi][2] = As_hi[(rb + g    )*36 + base + tig + 4];
                a_hi[mi][3] = As_hi[(rb + 8 + g)*36 + base + tig + 4];
            }
#pragma unroll
            for (int ni = 0; ni < 4; ni++) {
                int nb = wn*32 + ni*8;
                b_hi[ni][0] = Ws_hi[(nb + g)*36 + base + tig];
                b_hi[ni][1] = Ws_hi[(nb + g)*36 + base + tig + 4];
            }
            if (HILO) {
                unsigned a_lo[2][4], b_lo[4][2];
#pragma unroll
                for (int mi = 0; mi < 2; mi++) {
                    int rb = wm*32 + mi*16;
                    a_lo[mi][0] = As_lo[(rb + g    )*36 + base + tig];
                    a_lo[mi][1] = As_lo[(rb + 8 + g)*36 + base + tig];
                    a_lo[mi][2] = As_lo[(rb + g    )*36 + base + tig + 4];
                    a_lo[mi][3] = As_lo[(rb + 8 + g)*36 + base + tig + 4];
                }
#pragma unroll
                for (int ni = 0; ni < 4; ni++) {
                    int nb = wn*32 + ni*8;
                    b_lo[ni][0] = Ws_lo[(nb + g)*36 + base + tig];
                    b_lo[ni][1] = Ws_lo[(nb + g)*36 + base + tig + 4];
                }
#pragma unroll
                for (int mi = 0; mi < 2; mi++)
#pragma unroll
                    for (int ni = 0; ni < 4; ni++) {
                        mma8(acc[mi][ni], a_hi[mi], b_lo[ni]);
                        mma8(acc[mi][ni], a_lo[mi], b_hi[ni]);
                        mma8(acc[mi][ni], a_hi[mi], b_hi[ni]);
                    }
            } else {
#pragma unroll
                for (int mi = 0; mi < 2; mi++)
#pragma unroll
                    for (int ni = 0; ni < 4; ni++)
                        mma8(acc[mi][ni], a_hi[mi], b_hi[ni]);
            }
        }
        __syncthreads();
    }

    // epilogue
#pragma unroll
    for (int mi = 0; mi < 2; mi++) {
#pragma unroll
        for (int ni = 0; ni < 4; ni++) {
            int cb = n0 + wn*32 + ni*8 + 2*tig;
            float2 bb = *(const float2*)&bias[cb];
#pragma unroll
            for (int h = 0; h < 2; h++) {
                int row = row0 + wm*32 + mi*16 + g + h*8;
                if (row >= S) continue;
                float v0 = acc[mi][ni][h*2 + 0] + bb.x;
                float v1 = acc[mi][ni][h*2 + 1] + bb.y;
                if (ACT == 1) {
                    v0 = 0.5f * v0 * (1.f + erff(v0 * 0.70710678118654752f));
                    v1 = 0.5f * v1 * (1.f + erff(v1 * 0.70710678118654752f));
                } else if (ACT == 2) {
                    v0 = v0 / (1.f + expf(-v0));
                    v1 = v1 / (1.f + expf(-v1));
                }
                if (RES) {
                    float2 rr = *(const float2*)&Rb[(size_t)row * N + cb];
                    v0 += rr.x; v1 += rr.y;
                }
                *(float2*)&Cb[(size_t)row * N + cb] = make_float2(v0, v1);
            }
        }
    }
}

// ---------------- logits: lf[p] = h1[p]·aw2 + ab2 (warp per pixel) --------------
__global__ void logits_kernel(const float* __restrict__ aw2,
                              const float* __restrict__ ab2)
{
    int p = blockIdx.x * 8 + (threadIdx.x >> 5);
    int lane = threadIdx.x & 31;
    const float* h = g_h1 + (size_t)p * AGH;
    float s = 0.f;
#pragma unroll
    for (int j = 0; j < 16; j++) s += h[lane + 32*j] * aw2[lane + 32*j];
#pragma unroll
    for (int o = 16; o > 0; o >>= 1) s += __shfl_xor_sync(0xffffffffu, s, o);
    if (lane == 0) g_lf[p] = s + ab2[0];
}

// ---------------- selection + top-64 fallback + compaction ----------------------
__global__ void select_kernel()
{
    __shared__ float vals[NTOK];
    __shared__ int   sels[NTOK];
    __shared__ int   wtot[8];
    __shared__ int   scount;
    __shared__ float rv[256];
    __shared__ int   ri[256];
    int b = blockIdx.x, tid = threadIdx.x;
    int lane = tid & 31, w = tid >> 5;

    int localc = 0;
    for (int n = tid; n < NTOK; n += 256) {
        float v = g_lf[b*NTOK + n];
        vals[n] = v;
        int s = (v > 0.f) ? 1 : 0;
        sels[n] = s;
        g_maskf[b*NTOK + n] = s ? 1.f : 0.f;
        localc += s;
    }
    {
        int c = localc;
#pragma unroll
        for (int o = 16; o > 0; o >>= 1) c += __shfl_xor_sync(0xffffffffu, c, o);
        if (lane == 0) wtot[w] = c;
        __syncthreads();
        if (tid == 0) { int t = 0; for (int i = 0; i < 8; i++) t += wtot[i]; scount = t; }
        __syncthreads();
    }
    int count = scount;

    if (count < 64) {
        for (int n = tid; n < NTOK; n += 256) sels[n] = 0;
        __syncthreads();
        for (int iter = 0; iter < 64; iter++) {
            float bv = -1e38f; int bi = NTOK;
            for (int n = tid; n < NTOK; n += 256)
                if (!sels[n] && vals[n] > bv) { bv = vals[n]; bi = n; }
            rv[tid] = bv; ri[tid] = bi;
            __syncthreads();
            for (int o = 128; o > 0; o >>= 1) {
                if (tid < o) {
                    if (rv[tid+o] > rv[tid] ||
                        (rv[tid+o] == rv[tid] && ri[tid+o] < ri[tid])) {
                        rv[tid] = rv[tid+o]; ri[tid] = ri[tid+o];
                    }
                }
                __syncthreads();
            }
            if (tid == 0) sels[ri[0]] = 1;
            __syncthreads();
        }
    }

    // compaction: chunk of 9 per thread; two-level shfl scan for offsets
    int base = tid * 9;
    int lc = 0;
#pragma unroll
    for (int k = 0; k < 9; k++) lc += sels[base + k];
    int inc = lc;
#pragma unroll
    for (int o = 1; o < 32; o <<= 1) {
        int v = __shfl_up_sync(0xffffffffu, inc, o);
        if (lane >= o) inc += v;
    }
    if (lane == 31) wtot[w] = inc;
    __syncthreads();
    if (tid < 8) {
        int v = wtot[tid];
#pragma unroll
        for (int o = 1; o < 8; o <<= 1) {
            int u = __shfl_up_sync(0xffu, v, o);
            if (tid >= o) v += u;
        }
        wtot[tid] = v;
    }
    __syncthreads();
    int pos = inc - lc + (w ? wtot[w-1] : 0);
    if (tid == 0) g_S[b] = wtot[7];
#pragma unroll
    for (int k = 0; k < 9; k++)
        if (sels[base + k]) g_idx[b*NTOK + pos++] = base + k;
}

// ---------------- gather compacted tokens (both modules) ------------------------
__global__ void gather_kernel()
{
    int b = blockIdx.y, s = blockIdx.x;
    if (s >= g_S[b]) return;
    int n = g_idx[b*NTOK + s];
    int c = threadIdx.x;
    const float* src = g_Xall + ((size_t)b*NTOK + n)*512;
    g_X[((size_t)b*NTOK + s)*DIM + c]        = src[c];
    g_X[((size_t)(NB + b)*NTOK + s)*DIM + c] = src[256 + c];
}

// ---------------- LayerNorm (warp per token) ------------------------------------
__global__ void ln_kernel(const float* __restrict__ X,
                          const float* __restrict__ g0, const float* __restrict__ b0_,
                          const float* __restrict__ g1, const float* __restrict__ b1_,
                          float* __restrict__ O)
{
    int z = blockIdx.y;
    int b = z & (NB - 1);
    int t = blockIdx.x * 8 + (threadIdx.x >> 5);
    if (t >= g_S[b]) return;
    const float* gg = (z < NB) ? g0 : g1;
    const float* bb = (z < NB) ? b0_ : b1_;
    int lane = threadIdx.x & 31;
    const float* x = X + ((size_t)z*NTOK + t)*DIM;
    float v[8];
    float s = 0.f;
#pragma unroll
    for (int j = 0; j < 8; j++) { v[j] = x[lane + 32*j]; s += v[j]; }
#pragma unroll
    for (int o = 16; o > 0; o >>= 1) s += __shfl_xor_sync(0xffffffffu, s, o);
    float mean = s * (1.f/256.f);
    float vs = 0.f;
#pragma unroll
    for (int j = 0; j < 8; j++) { float d = v[j] - mean; vs += d*d; }
#pragma unroll
    for (int o = 16; o > 0; o >>= 1) vs += __shfl_xor_sync(0xffffffffu, vs, o);
    float rstd = rsqrtf(vs * (1.f/256.f) + 1e-5f);
    float* o = O + ((size_t)z*NTOK + t)*DIM;
#pragma unroll
    for (int j = 0; j < 8; j++) {
        int c = lane + 32*j;
        o[c] = (v[j] - mean) * rstd * gg[c] + bb[c];
    }
}

// ---------------- flash attention, tf32 mma, scalar LDS (dh=64, 4 heads) --------
__global__ void flash_kernel()
{
    extern __shared__ unsigned fsm[];
    unsigned* Qs  = fsm;                 // [q][d] tf32, stride 68
    unsigned* Ks  = fsm + 64*68;         // [k][d] tf32
    unsigned* Vst = fsm + 2*64*68;       // [d][key] tf32 (transposed)
    float*    Ss  = (float*)(fsm + 3*64*68);   // [q][k] scores / p(tf32)
    unsigned* Psu = fsm + 3*64*68;
    __shared__ float m_s[64], l_s[64], al_s[64];

    int z = blockIdx.z;
    int b = z & (NB - 1);
    int h = blockIdx.y;
    int S = g_S[b];
    int qb = blockIdx.x * 64;
    if (qb >= S) return;
    int tid = threadIdx.x;
    int warp = tid >> 5, lane = tid & 31;
    int g = lane >> 2, tig = lane & 3;
    int wm = warp >> 1, wn = warp & 1;
    const float* qkvb = g_qkv + (size_t)z * NTOK * 768;

    // load Q tile
#pragma unroll
    for (int it = 0; it < 4; it++) {
        int lin = tid + it * 256;
        int r = lin >> 4, c4 = (lin & 15) * 4;
        int t = qb + r;
        float4 v = make_float4(0.f, 0.f, 0.f, 0.f);
        if (t < S) v = *(const float4*)&qkvb[(size_t)t*768 + h*64 + c4];
        uint4 hv; hv.x = f2tf(v.x); hv.y = f2tf(v.y); hv.z = f2tf(v.z); hv.w = f2tf(v.w);
        *(uint4*)&Qs[r*68 + c4] = hv;
    }
    if (tid < 64) { m_s[tid] = -1e30f; l_s[tid] = 0.f; }

    float oacc[4][4];
#pragma unroll
    for (int ni = 0; ni < 4; ni++)
#pragma unroll
        for (int q = 0; q < 4; q++) oacc[ni][q] = 0.f;

    for (int kb = 0; kb < S; kb += 64) {
        __syncthreads();
        // load K tile
#pragma unroll
        for (int it = 0; it < 4; it++) {
            int lin = tid + it * 256;
            int r = lin >> 4, c4 = (lin & 15) * 4;
            int t = kb + r;
            float4 v = make_float4(0.f, 0.f, 0.f, 0.f);
            if (t < S) v = *(const float4*)&qkvb[(size_t)t*768 + 256 + h*64 + c4];
            uint4 hv; hv.x = f2tf(v.x); hv.y = f2tf(v.y); hv.z = f2tf(v.z); hv.w = f2tf(v.w);
            *(uint4*)&Ks[r*68 + c4] = hv;
        }
        // load V transposed: Vst[d][key]
#pragma unroll
        for (int it = 0; it < 16; it++) {
            int lin = tid + it * 256;
            int d = lin & 63, tt = lin >> 6;
            int t = kb + tt;
            float v = (t < S) ? qkvb[(size_t)t*768 + 512 + h*64 + d] : 0.f;
            Vst[d*68 + tt] = f2tf(v);
        }
        __syncthreads();

        // S = Q K^T (warp tile m16 x n32)
        float sacc[4][4];
#pragma unroll
        for (int ni = 0; ni < 4; ni++)
#pragma unroll
            for (int q = 0; q < 4; q++) sacc[ni][q] = 0.f;
#pragma unroll
        for (int ks = 0; ks < 8; ks++) {
            int base = ks * 8;
            unsigned a[4];
            int rb = wm * 16;
            a[0] = Qs[(rb + g    )*68 + base + tig];
            a[1] = Qs[(rb + 8 + g)*68 + base + tig];
            a[2] = Qs[(rb + g    )*68 + base + tig + 4];
            a[3] = Qs[(rb + 8 + g)*68 + base + tig + 4];
#pragma unroll
            for (int ni = 0; ni < 4; ni++) {
                int key = wn*32 + ni*8 + g;
                unsigned bf[2];
                bf[0] = Ks[key*68 + base + tig];
                bf[1] = Ks[key*68 + base + tig + 4];
                mma8(sacc[ni], a, bf);
            }
        }
        // scale + mask + store scores
#pragma unroll
        for (int ni = 0; ni < 4; ni++) {
            int kcol = wn*32 + ni*8 + 2*tig;
            int q0 = wm*16 + g;
            float s0 = sacc[ni][0] * 0.125f, s1 = sacc[ni][1] * 0.125f;
            float s2 = sacc[ni][2] * 0.125f, s3 = sacc[ni][3] * 0.125f;
            if (kb + kcol     >= S) { s0 = -1e30f; s2 = -1e30f; }
            if (kb + kcol + 1 >= S) { s1 = -1e30f; s3 = -1e30f; }
            *(float2*)&Ss[q0*68 + kcol]     = make_float2(s0, s1);
            *(float2*)&Ss[(q0+8)*68 + kcol] = make_float2(s2, s3);
        }
        __syncthreads();

        // online softmax (4 threads per row)
        {
            int row = tid >> 2, sub = tid & 3;
            float* Sr = Ss + row*68;
            float vv[16];
            float rm = -1e30f;
#pragma unroll
            for (int j = 0; j < 16; j++) { vv[j] = Sr[sub + 4*j]; rm = fmaxf(rm, vv[j]); }
            rm = fmaxf(rm, __shfl_xor_sync(0xffffffffu, rm, 1));
            rm = fmaxf(rm, __shfl_xor_sync(0xffffffffu, rm, 2));
            float mo = m_s[row];
            float mn = fmaxf(mo, rm);
            float rs = 0.f;
#pragma unroll
            for (int j = 0; j < 16; j++) {
                float p = __expf(vv[j] - mn);
                rs += p;
                Sr[sub + 4*j] = __uint_as_float(f2tf(p));
            }
            rs += __shfl_xor_sync(0xffffffffu, rs, 1);
            rs += __shfl_xor_sync(0xffffffffu, rs, 2);
            if (sub == 0) {
                float al = __expf(mo - mn);
                l_s[row] = l_s[row] * al + rs;
                m_s[row] = mn;
                al_s[row] = al;
            }
        }
        __syncthreads();

        // rescale O accumulators
        {
            float al0 = al_s[wm*16 + g];
            float al1 = al_s[wm*16 + 8 + g];
#pragma unroll
            for (int ni = 0; ni < 4; ni++) {
                oacc[ni][0] *= al0; oacc[ni][1] *= al0;
                oacc[ni][2] *= al1; oacc[ni][3] *= al1;
            }
        }

        // O += P V (A = P rows q, B = Vst[d][key])
#pragma unroll
        for (int ks = 0; ks < 8; ks++) {
            int base = ks * 8;
            unsigned a[4];
            int rb = wm * 16;
            a[0] = Psu[(rb + g    )*68 + base + tig];
            a[1] = Psu[(rb + 8 + g)*68 + base + tig];
            a[2] = Psu[(rb + g    )*68 + base + tig + 4];
            a[3] = Psu[(rb + 8 + g)*68 + base + tig + 4];
#pragma unroll
            for (int ni = 0; ni < 4; ni++) {
                int d = wn*32 + ni*8 + g;
                unsigned bf[2];
                bf[0] = Vst[d*68 + base + tig];
                bf[1] = Vst[d*68 + base + tig + 4];
                mma8(oacc[ni], a, bf);
            }
        }
    }

    // final normalize + store
    {
        int q0 = wm*16 + g;
        float il0 = 1.f / l_s[q0];
        float il1 = 1.f / l_s[q0 + 8];
        int t0 = qb + q0, t1 = qb + q0 + 8;
        float* ab = g_attn + (size_t)z * NTOK * DIM;
#pragma unroll
        for (int ni = 0; ni < 4; ni++) {
            int d = h*64 + wn*32 + ni*8 + 2*tig;
            if (t0 < S)
                *(float2*)&ab[(size_t)t0*DIM + d] = make_float2(oacc[ni][0]*il0, oacc[ni][1]*il0);
            if (t1 < S)
                *(float2*)&ab[(size_t)t1*DIM + d] = make_float2(oacc[ni][2]*il1, oacc[ni][3]*il1);
        }
    }
}

// ---------------- final scatter -------------------------------------------------
__global__ void scatter_kernel(float* __restrict__ out)
{
    int b = blockIdx.y, s = blockIdx.x;
    if (s >= g_S[b]) return;
    int n = g_idx[b*NTOK + s];
    int c = threadIdx.x;
    float v = (g_mix[((size_t)b*NTOK + s)*DIM + c] +
               g_mix[((size_t)(NB + b)*NTOK + s)*DIM + c]) * g_maskf[b*NTOK + n];
    out[((size_t)b*DIM + c)*NTOK + n] = v;
}

// ---------------- host ----------------------------------------------------------
#define GETSYM(ptr, sym) cudaGetSymbolAddress((void**)&(ptr), sym)

extern "C" void kernel_launch(void* const* d_in, const int* in_sizes, int n_in,
                              void* d_out, int out_size)
{
    const float* f_ir  = (const float*)d_in[0];
    const float* f_vis = (const float*)d_in[1];
    const float* aw1   = (const float*)d_in[2];
    const float* ab1   = (const float*)d_in[3];
    const float* aw2   = (const float*)d_in[4];
    const float* ab2   = (const float*)d_in[5];
    const float* P[20];
    for (int i = 0; i < 20; i++) P[i] = (const float*)d_in[6 + i];
    float* out = (float*)d_out;

    float *p_Xall, *p_h1, *p_X, *p_xn, *p_qkv, *p_attn, *p_x1, *p_hff, *p_mix;
    GETSYM(p_Xall, g_Xall); GETSYM(p_h1, g_h1); GETSYM(p_X, g_X);
    GETSYM(p_xn, g_xn);     GETSYM(p_qkv, g_qkv); GETSYM(p_attn, g_attn);
    GETSYM(p_x1, g_x1);     GETSYM(p_hff, g_hff); GETSYM(p_mix, g_mix);

    const int SM1 = 192*36*4;      // 27648 B : single tf32
    const int SM3 = 384*36*4;      // 55296 B : 3xTF32
    const int SMF = 4*64*68*4;     // 69632 B : flash

    cudaFuncSetAttribute(tgemm<2,false,false,true>, cudaFuncAttributeMaxDynamicSharedMemorySize, SM3);
    cudaFuncSetAttribute(tgemm<0,false,true,false>, cudaFuncAttributeMaxDynamicSharedMemorySize, SM1);
    cudaFuncSetAttribute(tgemm<0,true ,true,false>, cudaFuncAttributeMaxDynamicSharedMemorySize, SM1);
    cudaFuncSetAttribute(tgemm<1,false,true,false>, cudaFuncAttributeMaxDynamicSharedMemorySize, SM1);
    cudaFuncSetAttribute(flash_kernel, cudaFuncAttributeMaxDynamicSharedMemorySize, SMF);

    prep_kernel<<<dim3(72, 8, NB), dim3(32, 8)>>>(f_ir, f_vis, out);
    // agent: 3xTF32 (fp32-grade; logit sign decisions are razor-thin), silu
    tgemm<2,false,false,true><<<dim3(18, 8, NB), 256, SM3>>>(
        p_Xall, aw1, aw1, ab1, ab1, nullptr, p_h1, 512, 512);
    logits_kernel<<<1152, 256>>>(aw2, ab2);
    select_kernel<<<NB, 256>>>();
    gather_kernel<<<dim3(NTOK, NB), 256>>>();

    // fused ir+vis mixer pipeline: z = mod*NB + b (8 slots)
    ln_kernel<<<dim3(288, 8), 256>>>(p_X, P[0], P[1], P[10], P[11], p_xn);
    tgemm<0,false,true,false><<<dim3(18, 12, 8), 256, SM1>>>(
        p_xn, P[2], P[12], P[3], P[13], nullptr, p_qkv, 256, 768);
    flash_kernel<<<dim3(36, 4, 8), 256, SMF>>>();
    tgemm<0,true,true,false><<<dim3(18, 4, 8), 256, SM1>>>(
        p_attn, P[4], P[14], P[5], P[15], p_X, p_x1, 256, 256);
    ln_kernel<<<dim3(288, 8), 256>>>(p_x1, P[0], P[1], P[10], P[11], p_xn);
    tgemm<1,false,true,false><<<dim3(18, 16, 8), 256, SM1>>>(
        p_xn, P[6], P[16], P[7], P[17], nullptr, p_hff, 256, 1024);
    tgemm<0,true,true,false><<<dim3(18, 4, 8), 256, SM1>>>(
        p_hff, P[8], P[18], P[9], P[19], p_x1, p_mix, 1024, 256);

    scatter_kernel<<<dim3(NTOK, NB), 256>>>(out);
}

// round 9
// speedup vs baseline: 1.4713x; 1.4713x over previous
#include <cuda_runtime.h>
#include <math.h>

#define NB   4
#define NTOK 2304
#define DIM  256
#define AGH  512

// ---------------- scratch (device globals; no allocation allowed) ----------------
__device__ float g_Xall[NB*NTOK*512];          // [b][n][c] c=0..255 ir, 256..511 vis
__device__ float g_h1[NB*NTOK*AGH];
__device__ float g_lf[NB*NTOK];
__device__ float g_maskf[NB*NTOK];
__device__ int   g_idx[NB*NTOK];
__device__ int   g_S[NB];
__device__ float g_X[2*NB*NTOK*DIM];           // compacted tokens, slot = mod*NB+b
__device__ float g_xn[2*NB*NTOK*DIM];
__device__ float g_qkv[2*NB*NTOK*3*DIM];
__device__ float g_attn[2*NB*NTOK*DIM];
__device__ float g_x1[2*NB*NTOK*DIM];
__device__ float g_hff[2*NB*NTOK*4*DIM];
__device__ float g_mix[2*NB*NTOK*DIM];

// ---------------- tf32 / cp.async helpers ---------------------------------------
__device__ __forceinline__ unsigned f2tf(float x) {
    unsigned u; asm("cvt.rna.tf32.f32 %0, %1;" : "=r"(u) : "f"(x)); return u;
}
__device__ __forceinline__ void mma8(float (&c)[4], const unsigned (&a)[4],
                                     const unsigned (&b)[2]) {
    asm volatile(
        "mma.sync.aligned.m16n8k8.row.col.f32.tf32.tf32.f32 "
        "{%0,%1,%2,%3}, {%4,%5,%6,%7}, {%8,%9}, {%0,%1,%2,%3};"
        : "+f"(c[0]), "+f"(c[1]), "+f"(c[2]), "+f"(c[3])
        : "r"(a[0]), "r"(a[1]), "r"(a[2]), "r"(a[3]), "r"(b[0]), "r"(b[1]));
}
__device__ __forceinline__ void cpa16(float* dst, const float* src, bool pred) {
    unsigned d = (unsigned)__cvta_generic_to_shared(dst);
    int sz = pred ? 16 : 0;
    asm volatile("cp.async.cg.shared.global [%0], [%1], 16, %2;"
                 :: "r"(d), "l"(src), "r"(sz));
}
#define CP_COMMIT() asm volatile("cp.async.commit_group;" ::: "memory")

// ---------------- prep: transpose to token-major concat + base canvas -----------
__global__ void prep_kernel(const float* __restrict__ f_ir,
                            const float* __restrict__ f_vis,
                            float* __restrict__ out)
{
    __shared__ float ti[32][33], tv[32][33];
    int b = blockIdx.z;
    int c0 = blockIdx.y * 32;
    int n0 = blockIdx.x * 32;
#pragma unroll
    for (int i = 0; i < 4; i++) {
        int c = c0 + threadIdx.y + i * 8;
        size_t off = ((size_t)b*256 + c)*NTOK + n0 + threadIdx.x;
        float vi = f_ir[off], vv = f_vis[off];
        ti[threadIdx.y + i*8][threadIdx.x] = vi;
        tv[threadIdx.y + i*8][threadIdx.x] = vv;
        out[off] = vi + vv;
    }
    __syncthreads();
#pragma unroll
    for (int i = 0; i < 4; i++) {
        int n = n0 + threadIdx.y + i * 8;
        size_t base = ((size_t)b*NTOK + n)*512;
        g_Xall[base + c0 + threadIdx.x]       = ti[threadIdx.x][threadIdx.y + i*8];
        g_Xall[base + 256 + c0 + threadIdx.x] = tv[threadIdx.x][threadIdx.y + i*8];
    }
}

// ---------------- generic tf32 tensor-core GEMM, cp.async double-buffer ---------
// block tile 128(M) x 64(N), K-chunk 32, 8 warps (4 M x 2 N), warp tile 32x32.
// smem holds raw fp32; cvt to tf32 happens at fragment load (identical values).
// HILO: 3xTF32 fp32-grade accuracy (agent path — logits sit near zero).
template<int ACT, bool RES, bool USE_S, bool HILO>
__global__ void __launch_bounds__(256) tgemm(
                      const float* __restrict__ A,
                      const float* __restrict__ W0, const float* __restrict__ W1,
                      const float* __restrict__ bias0, const float* __restrict__ bias1,
                      const float* __restrict__ R, float* __restrict__ C,
                      int K, int N)
{
    int z = blockIdx.z;
    int b = z & (NB - 1);
    int S = USE_S ? g_S[b] : NTOK;
    int row0 = blockIdx.x * 128;
    if (row0 >= S) return;
    const float* W    = (z < NB) ? W0 : W1;
    const float* bias = (z < NB) ? bias0 : bias1;
    int n0 = blockIdx.y * 64;
    const float* Ab = A + (size_t)z * NTOK * K;
    float*       Cb = C + (size_t)z * NTOK * N;
    const float* Rb = RES ? (R + (size_t)z * NTOK * N) : nullptr;

    extern __shared__ float sh[];                    // 2 x (A 128*36 + W 64*36)
    float* Abuf[2] = { sh,            sh + 192*36 };
    float* Wbuf[2] = { sh + 128*36,   sh + 320*36 };

    int tid  = threadIdx.x;
    int warp = tid >> 5, lane = tid & 31;
    int g = lane >> 2, tig = lane & 3;
    int wm = warp >> 1, wn = warp & 1;

    // staging coordinates (fixed)
    int ar  = tid >> 3;              // 0..31; + it*32 covers rows
    int ac4 = (tid & 7) * 4;         // col group (16B)

    float acc[2][4][4];
#pragma unroll
    for (int mi = 0; mi < 2; mi++)
#pragma unroll
        for (int ni = 0; ni < 4; ni++)
#pragma unroll
            for (int q = 0; q < 4; q++) acc[mi][ni][q] = 0.f;

    const int NCH = K >> 5;

    // issue chunk c into buffer bi
    auto issue = [&](int c, int bi) {
        int kc = c * 32;
#pragma unroll
        for (int it = 0; it < 4; it++) {
            int r = ar + it * 32;
            int row = row0 + r;
            bool ok = (row < S);
            cpa16(&Abuf[bi][r*36 + ac4], &Ab[(size_t)(ok ? row : 0) * K + kc + ac4], ok);
        }
#pragma unroll
        for (int it = 0; it < 2; it++) {
            int r = ar + it * 32;        // 0..63 = W tile row
            cpa16(&Wbuf[bi][r*36 + ac4], &W[(size_t)(n0 + r) * K + kc + ac4], true);
        }
    };

    issue(0, 0);
    CP_COMMIT();

    for (int c = 0; c < NCH; c++) {
        int cur = c & 1;
        if (c + 1 < NCH) { issue(c + 1, cur ^ 1); CP_COMMIT(); }
        if (c + 1 < NCH) asm volatile("cp.async.wait_group 1;" ::: "memory");
        else             asm volatile("cp.async.wait_group 0;" ::: "memory");
        __syncthreads();

        const float* Asb = Abuf[cur];
        const float* Wsb = Wbuf[cur];
#pragma unroll
        for (int ks = 0; ks < 4; ks++) {
            int base = ks * 8;
            unsigned a_hi[2][4], b_hi[4][2];
            float a_f[2][4], b_f[4][2];
#pragma unroll
            for (int mi = 0; mi < 2; mi++) {
                int rb = wm*32 + mi*16;
                a_f[mi][0] = Asb[(rb + g    )*36 + base + tig];
                a_f[mi][1] = Asb[(rb + 8 + g)*36 + base + tig];
                a_f[mi][2] = Asb[(rb + g    )*36 + base + tig + 4];
                a_f[mi][3] = Asb[(rb + 8 + g)*36 + base + tig + 4];
#pragma unroll
                for (int q = 0; q < 4; q++) a_hi[mi][q] = f2tf(a_f[mi][q]);
            }
#pragma unroll
            for (int ni = 0; ni < 4; ni++) {
                int nb = wn*32 + ni*8;
                b_f[ni][0] = Wsb[(nb + g)*36 + base + tig];
                b_f[ni][1] = Wsb[(nb + g)*36 + base + tig + 4];
                b_hi[ni][0] = f2tf(b_f[ni][0]);
                b_hi[ni][1] = f2tf(b_f[ni][1]);
            }
            if (HILO) {
                unsigned a_lo[2][4], b_lo[4][2];
#pragma unroll
                for (int mi = 0; mi < 2; mi++)
#pragma unroll
                    for (int q = 0; q < 4; q++)
                        a_lo[mi][q] = f2tf(a_f[mi][q] - __uint_as_float(a_hi[mi][q]));
#pragma unroll
                for (int ni = 0; ni < 4; ni++) {
                    b_lo[ni][0] = f2tf(b_f[ni][0] - __uint_as_float(b_hi[ni][0]));
                    b_lo[ni][1] = f2tf(b_f[ni][1] - __uint_as_float(b_hi[ni][1]));
                }
#pragma unroll
                for (int mi = 0; mi < 2; mi++)
#pragma unroll
                    for (int ni = 0; ni < 4; ni++) {
                        mma8(acc[mi][ni], a_hi[mi], b_lo[ni]);
                        mma8(acc[mi][ni], a_lo[mi], b_hi[ni]);
                        mma8(acc[mi][ni], a_hi[mi], b_hi[ni]);
                    }
            } else {
#pragma unroll
                for (int mi = 0; mi < 2; mi++)
#pragma unroll
                    for (int ni = 0; ni < 4; ni++)
                        mma8(acc[mi][ni], a_hi[mi], b_hi[ni]);
            }
        }
        __syncthreads();
    }

    // epilogue
#pragma unroll
    for (int mi = 0; mi < 2; mi++) {
#pragma unroll
        for (int ni = 0; ni < 4; ni++) {
            int cb = n0 + wn*32 + ni*8 + 2*tig;
            float2 bb = *(const float2*)&bias[cb];
#pragma unroll
            for (int h = 0; h < 2; h++) {
                int row = row0 + wm*32 + mi*16 + g + h*8;
                if (row >= S) continue;
                float v0 = acc[mi][ni][h*2 + 0] + bb.x;
                float v1 = acc[mi][ni][h*2 + 1] + bb.y;
                if (ACT == 1) {
                    v0 = 0.5f * v0 * (1.f + erff(v0 * 0.70710678118654752f));
                    v1 = 0.5f * v1 * (1.f + erff(v1 * 0.70710678118654752f));
                } else if (ACT == 2) {
                    v0 = v0 / (1.f + expf(-v0));
                    v1 = v1 / (1.f + expf(-v1));
                }
                if (RES) {
                    float2 rr = *(const float2*)&Rb[(size_t)row * N + cb];
                    v0 += rr.x; v1 += rr.y;
                }
                *(float2*)&Cb[(size_t)row * N + cb] = make_float2(v0, v1);
            }
        }
    }
}

// ---------------- logits: lf[p] = h1[p]·aw2 + ab2 (warp per pixel) --------------
__global__ void logits_kernel(const float* __restrict__ aw2,
                              const float* __restrict__ ab2)
{
    int p = blockIdx.x * 8 + (threadIdx.x >> 5);
    int lane = threadIdx.x & 31;
    const float* h = g_h1 + (size_t)p * AGH;
    float s = 0.f;
#pragma unroll
    for (int j = 0; j < 16; j++) s += h[lane + 32*j] * aw2[lane + 32*j];
#pragma unroll
    for (int o = 16; o > 0; o >>= 1) s += __shfl_xor_sync(0xffffffffu, s, o);
    if (lane == 0) g_lf[p] = s + ab2[0];
}

// ---------------- selection + top-64 fallback + compaction ----------------------
__global__ void select_kernel()
{
    __shared__ float vals[NTOK];
    __shared__ int   sels[NTOK];
    __shared__ int   wtot[8];
    __shared__ int   scount;
    __shared__ float rv[256];
    __shared__ int   ri[256];
    int b = blockIdx.x, tid = threadIdx.x;
    int lane = tid & 31, w = tid >> 5;

    int localc = 0;
    for (int n = tid; n < NTOK; n += 256) {
        float v = g_lf[b*NTOK + n];
        vals[n] = v;
        int s = (v > 0.f) ? 1 : 0;
        sels[n] = s;
        g_maskf[b*NTOK + n] = s ? 1.f : 0.f;
        localc += s;
    }
    {
        int c = localc;
#pragma unroll
        for (int o = 16; o > 0; o >>= 1) c += __shfl_xor_sync(0xffffffffu, c, o);
        if (lane == 0) wtot[w] = c;
        __syncthreads();
        if (tid == 0) { int t = 0; for (int i = 0; i < 8; i++) t += wtot[i]; scount = t; }
        __syncthreads();
    }
    int count = scount;

    if (count < 64) {
        for (int n = tid; n < NTOK; n += 256) sels[n] = 0;
        __syncthreads();
        for (int iter = 0; iter < 64; iter++) {
            float bv = -1e38f; int bi = NTOK;
            for (int n = tid; n < NTOK; n += 256)
                if (!sels[n] && vals[n] > bv) { bv = vals[n]; bi = n; }
            rv[tid] = bv; ri[tid] = bi;
            __syncthreads();
            for (int o = 128; o > 0; o >>= 1) {
                if (tid < o) {
                    if (rv[tid+o] > rv[tid] ||
                        (rv[tid+o] == rv[tid] && ri[tid+o] < ri[tid])) {
                        rv[tid] = rv[tid+o]; ri[tid] = ri[tid+o];
                    }
                }
                __syncthreads();
            }
            if (tid == 0) sels[ri[0]] = 1;
            __syncthreads();
        }
    }

    // compaction: chunk of 9 per thread; two-level shfl scan for offsets
    int base = tid * 9;
    int lc = 0;
#pragma unroll
    for (int k = 0; k < 9; k++) lc += sels[base + k];
    int inc = lc;
#pragma unroll
    for (int o = 1; o < 32; o <<= 1) {
        int v = __shfl_up_sync(0xffffffffu, inc, o);
        if (lane >= o) inc += v;
    }
    if (lane == 31) wtot[w] = inc;
    __syncthreads();
    if (tid < 8) {
        int v = wtot[tid];
#pragma unroll
        for (int o = 1; o < 8; o <<= 1) {
            int u = __shfl_up_sync(0xffu, v, o);
            if (tid >= o) v += u;
        }
        wtot[tid] = v;
    }
    __syncthreads();
    int pos = inc - lc + (w ? wtot[w-1] : 0);
    if (tid == 0) g_S[b] = wtot[7];
#pragma unroll
    for (int k = 0; k < 9; k++)
        if (sels[base + k]) g_idx[b*NTOK + pos++] = base + k;
}

// ---------------- gather compacted tokens (both modules) ------------------------
__global__ void gather_kernel()
{
    int b = blockIdx.y, s = blockIdx.x;
    if (s >= g_S[b]) return;
    int n = g_idx[b*NTOK + s];
    int c = threadIdx.x;
    const float* src = g_Xall + ((size_t)b*NTOK + n)*512;
    g_X[((size_t)b*NTOK + s)*DIM + c]        = src[c];
    g_X[((size_t)(NB + b)*NTOK + s)*DIM + c] = src[256 + c];
}

// ---------------- LayerNorm (warp per token) ------------------------------------
__global__ void ln_kernel(const float* __restrict__ X,
                          const float* __restrict__ g0, const float* __restrict__ b0_,
                          const float* __restrict__ g1, const float* __restrict__ b1_,
                          float* __restrict__ O)
{
    int z = blockIdx.y;
    int b = z & (NB - 1);
    int t = blockIdx.x * 8 + (threadIdx.x >> 5);
    if (t >= g_S[b]) return;
    const float* gg = (z < NB) ? g0 : g1;
    const float* bb = (z < NB) ? b0_ : b1_;
    int lane = threadIdx.x & 31;
    const float* x = X + ((size_t)z*NTOK + t)*DIM;
    float v[8];
    float s = 0.f;
#pragma unroll
    for (int j = 0; j < 8; j++) { v[j] = x[lane + 32*j]; s += v[j]; }
#pragma unroll
    for (int o = 16; o > 0; o >>= 1) s += __shfl_xor_sync(0xffffffffu, s, o);
    float mean = s * (1.f/256.f);
    float vs = 0.f;
#pragma unroll
    for (int j = 0; j < 8; j++) { float d = v[j] - mean; vs += d*d; }
#pragma unroll
    for (int o = 16; o > 0; o >>= 1) vs += __shfl_xor_sync(0xffffffffu, vs, o);
    float rstd = rsqrtf(vs * (1.f/256.f) + 1e-5f);
    float* o = O + ((size_t)z*NTOK + t)*DIM;
#pragma unroll
    for (int j = 0; j < 8; j++) {
        int c = lane + 32*j;
        o[c] = (v[j] - mean) * rstd * gg[c] + bb[c];
    }
}

// ---------------- flash attention, tf32 mma, scalar LDS (dh=64, 4 heads) --------
__global__ void flash_kernel()
{
    extern __shared__ unsigned fsm[];
    unsigned* Qs  = fsm;                 // [q][d] tf32, stride 68
    unsigned* Ks  = fsm + 64*68;         // [k][d] tf32
    unsigned* Vst = fsm + 2*64*68;       // [d][key] tf32 (transposed)
    float*    Ss  = (float*)(fsm + 3*64*68);   // [q][k] scores / p(tf32)
    unsigned* Psu = fsm + 3*64*68;
    __shared__ float m_s[64], l_s[64], al_s[64];

    int z = blockIdx.z;
    int b = z & (NB - 1);
    int h = blockIdx.y;
    int S = g_S[b];
    int qb = blockIdx.x * 64;
    if (qb >= S) return;
    int tid = threadIdx.x;
    int warp = tid >> 5, lane = tid & 31;
    int g = lane >> 2, tig = lane & 3;
    int wm = warp >> 1, wn = warp & 1;
    const float* qkvb = g_qkv + (size_t)z * NTOK * 768;

    // load Q tile
#pragma unroll
    for (int it = 0; it < 4; it++) {
        int lin = tid + it * 256;
        int r = lin >> 4, c4 = (lin & 15) * 4;
        int t = qb + r;
        float4 v = make_float4(0.f, 0.f, 0.f, 0.f);
        if (t < S) v = *(const float4*)&qkvb[(size_t)t*768 + h*64 + c4];
        uint4 hv; hv.x = f2tf(v.x); hv.y = f2tf(v.y); hv.z = f2tf(v.z); hv.w = f2tf(v.w);
        *(uint4*)&Qs[r*68 + c4] = hv;
    }
    if (tid < 64) { m_s[tid] = -1e30f; l_s[tid] = 0.f; }

    float oacc[4][4];
#pragma unroll
    for (int ni = 0; ni < 4; ni++)
#pragma unroll
        for (int q = 0; q < 4; q++) oacc[ni][q] = 0.f;

    for (int kb = 0; kb < S; kb += 64) {
        __syncthreads();
        // load K tile
#pragma unroll
        for (int it = 0; it < 4; it++) {
            int lin = tid + it * 256;
            int r = lin >> 4, c4 = (lin & 15) * 4;
            int t = kb + r;
            float4 v = make_float4(0.f, 0.f, 0.f, 0.f);
            if (t < S) v = *(const float4*)&qkvb[(size_t)t*768 + 256 + h*64 + c4];
            uint4 hv; hv.x = f2tf(v.x); hv.y = f2tf(v.y); hv.z = f2tf(v.z); hv.w = f2tf(v.w);
            *(uint4*)&Ks[r*68 + c4] = hv;
        }
        // load V transposed: Vst[d][key]
#pragma unroll
        for (int it = 0; it < 16; it++) {
            int lin = tid + it * 256;
            int d = lin & 63, tt = lin >> 6;
            int t = kb + tt;
            float v = (t < S) ? qkvb[(size_t)t*768 + 512 + h*64 + d] : 0.f;
            Vst[d*68 + tt] = f2tf(v);
        }
        __syncthreads();

        // S = Q K^T (warp tile m16 x n32)
        float sacc[4][4];
#pragma unroll
        for (int ni = 0; ni < 4; ni++)
#pragma unroll
            for (int q = 0; q < 4; q++) sacc[ni][q] = 0.f;
#pragma unroll
        for (int ks = 0; ks < 8; ks++) {
            int base = ks * 8;
            unsigned a[4];
            int rb = wm * 16;
            a[0] = Qs[(rb + g    )*68 + base + tig];
            a[1] = Qs[(rb + 8 + g)*68 + base + tig];
            a[2] = Qs[(rb + g    )*68 + base + tig + 4];
            a[3] = Qs[(rb + 8 + g)*68 + base + tig + 4];
#pragma unroll
            for (int ni = 0; ni < 4; ni++) {
                int key = wn*32 + ni*8 + g;
                unsigned bf[2];
                bf[0] = Ks[key*68 + base + tig];
                bf[1] = Ks[key*68 + base + tig + 4];
                mma8(sacc[ni], a, bf);
            }
        }
        // scale + mask + store scores
#pragma unroll
        for (int ni = 0; ni < 4; ni++) {
            int kcol = wn*32 + ni*8 + 2*tig;
            int q0 = wm*16 + g;
            float s0 = sacc[ni][0] * 0.125f, s1 = sacc[ni][1] * 0.125f;
            float s2 = sacc[ni][2] * 0.125f, s3 = sacc[ni][3] * 0.125f;
            if (kb + kcol     >= S) { s0 = -1e30f; s2 = -1e30f; }
            if (kb + kcol + 1 >= S) { s1 = -1e30f; s3 = -1e30f; }
            *(float2*)&Ss[q0*68 + kcol]     = make_float2(s0, s1);
            *(float2*)&Ss[(q0+8)*68 + kcol] = make_float2(s2, s3);
        }
        __syncthreads();

        // online softmax (4 threads per row)
        {
            int row = tid >> 2, sub = tid & 3;
            float* Sr = Ss + row*68;
            float vv[16];
            float rm = -1e30f;
#pragma unroll
            for (int j = 0; j < 16; j++) { vv[j] = Sr[sub + 4*j]; rm = fmaxf(rm, vv[j]); }
            rm = fmaxf(rm, __shfl_xor_sync(0xffffffffu, rm, 1));
            rm = fmaxf(rm, __shfl_xor_sync(0xffffffffu, rm, 2));
            float mo = m_s[row];
            float mn = fmaxf(mo, rm);
            float rs = 0.f;
#pragma unroll
            for (int j = 0; j < 16; j++) {
                float p = __expf(vv[j] - mn);
                rs += p;
                Sr[sub + 4*j] = __uint_as_float(f2tf(p));
            }
            rs += __shfl_xor_sync(0xffffffffu, rs, 1);
            rs += __shfl_xor_sync(0xffffffffu, rs, 2);
            if (sub == 0) {
                float al = __expf(mo - mn);
                l_s[row] = l_s[row] * al + rs;
                m_s[row] = mn;
                al_s[row] = al;
            }
        }
        __syncthreads();

        // rescale O accumulators
        {
            float al0 = al_s[wm*16 + g];
            float al1 = al_s[wm*16 + 8 + g];
#pragma unroll
            for (int ni = 0; ni < 4; ni++) {
                oacc[ni][0] *= al0; oacc[ni][1] *= al0;
                oacc[ni][2] *= al1; oacc[ni][3] *= al1;
            }
        }

        // O += P V (A = P rows q, B = Vst[d][key])
#pragma unroll
        for (int ks = 0; ks < 8; ks++) {
            int base = ks * 8;
            unsigned a[4];
            int rb = wm * 16;
            a[0] = Psu[(rb + g    )*68 + base + tig];
            a[1] = Psu[(rb + 8 + g)*68 + base + tig];
            a[2] = Psu[(rb + g    )*68 + base + tig + 4];
            a[3] = Psu[(rb + 8 + g)*68 + base + tig + 4];
#pragma unroll
            for (int ni = 0; ni < 4; ni++) {
                int d = wn*32 + ni*8 + g;
                unsigned bf[2];
                bf[0] = Vst[d*68 + base + tig];
                bf[1] = Vst[d*68 + base + tig + 4];
                mma8(oacc[ni], a, bf);
            }
        }
    }

    // final normalize + store
    {
        int q0 = wm*16 + g;
        float il0 = 1.f / l_s[q0];
        float il1 = 1.f / l_s[q0 + 8];
        int t0 = qb + q0, t1 = qb + q0 + 8;
        float* ab = g_attn + (size_t)z * NTOK * DIM;
#pragma unroll
        for (int ni = 0; ni < 4; ni++) {
            int d = h*64 + wn*32 + ni*8 + 2*tig;
            if (t0 < S)
                *(float2*)&ab[(size_t)t0*DIM + d] = make_float2(oacc[ni][0]*il0, oacc[ni][1]*il0);
            if (t1 < S)
                *(float2*)&ab[(size_t)t1*DIM + d] = make_float2(oacc[ni][2]*il1, oacc[ni][3]*il1);
        }
    }
}

// ---------------- final scatter -------------------------------------------------
__global__ void scatter_kernel(float* __restrict__ out)
{
    int b = blockIdx.y, s = blockIdx.x;
    if (s >= g_S[b]) return;
    int n = g_idx[b*NTOK + s];
    int c = threadIdx.x;
    float v = (g_mix[((size_t)b*NTOK + s)*DIM + c] +
               g_mix[((size_t)(NB + b)*NTOK + s)*DIM + c]) * g_maskf[b*NTOK + n];
    out[((size_t)b*DIM + c)*NTOK + n] = v;
}

// ---------------- host ----------------------------------------------------------
#define GETSYM(ptr, sym) cudaGetSymbolAddress((void**)&(ptr), sym)

extern "C" void kernel_launch(void* const* d_in, const int* in_sizes, int n_in,
                              void* d_out, int out_size)
{
    const float* f_ir  = (const float*)d_in[0];
    const float* f_vis = (const float*)d_in[1];
    const float* aw1   = (const float*)d_in[2];
    const float* ab1   = (const float*)d_in[3];
    const float* aw2   = (const float*)d_in[4];
    const float* ab2   = (const float*)d_in[5];
    const float* P[20];
    for (int i = 0; i < 20; i++) P[i] = (const float*)d_in[6 + i];
    float* out = (float*)d_out;

    float *p_Xall, *p_h1, *p_X, *p_xn, *p_qkv, *p_attn, *p_x1, *p_hff, *p_mix;
    GETSYM(p_Xall, g_Xall); GETSYM(p_h1, g_h1); GETSYM(p_X, g_X);
    GETSYM(p_xn, g_xn);     GETSYM(p_qkv, g_qkv); GETSYM(p_attn, g_attn);
    GETSYM(p_x1, g_x1);     GETSYM(p_hff, g_hff); GETSYM(p_mix, g_mix);

    const int SMG = 2*192*36*4;    // 55296 B : double-buffered fp32 tiles
    const int SMF = 4*64*68*4;     // 69632 B : flash

    cudaFuncSetAttribute(tgemm<2,false,false,true>, cudaFuncAttributeMaxDynamicSharedMemorySize, SMG);
    cudaFuncSetAttribute(tgemm<0,false,true,false>, cudaFuncAttributeMaxDynamicSharedMemorySize, SMG);
    cudaFuncSetAttribute(tgemm<0,true ,true,false>, cudaFuncAttributeMaxDynamicSharedMemorySize, SMG);
    cudaFuncSetAttribute(tgemm<1,false,true,false>, cudaFuncAttributeMaxDynamicSharedMemorySize, SMG);
    cudaFuncSetAttribute(flash_kernel, cudaFuncAttributeMaxDynamicSharedMemorySize, SMF);

    prep_kernel<<<dim3(72, 8, NB), dim3(32, 8)>>>(f_ir, f_vis, out);
    // agent: 3xTF32 (fp32-grade; logit sign decisions are razor-thin), silu
    tgemm<2,false,false,true><<<dim3(18, 8, NB), 256, SMG>>>(
        p_Xall, aw1, aw1, ab1, ab1, nullptr, p_h1, 512, 512);
    logits_kernel<<<1152, 256>>>(aw2, ab2);
    select_kernel<<<NB, 256>>>();
    gather_kernel<<<dim3(NTOK, NB), 256>>>();

    // fused ir+vis mixer pipeline: z = mod*NB + b (8 slots)
    ln_kernel<<<dim3(288, 8), 256>>>(p_X, P[0], P[1], P[10], P[11], p_xn);
    tgemm<0,false,true,false><<<dim3(18, 12, 8), 256, SMG>>>(
        p_xn, P[2], P[12], P[3], P[13], nullptr, p_qkv, 256, 768);
    flash_kernel<<<dim3(36, 4, 8), 256, SMF>>>();
    tgemm<0,true,true,false><<<dim3(18, 4, 8), 256, SMG>>>(
        p_attn, P[4], P[14], P[5], P[15], p_X, p_x1, 256, 256);
    ln_kernel<<<dim3(288, 8), 256>>>(p_x1, P[0], P[1], P[10], P[11], p_xn);
    tgemm<1,false,true,false><<<dim3(18, 16, 8), 256, SMG>>>(
        p_xn, P[6], P[16], P[7], P[17], nullptr, p_hff, 256, 1024);
    tgemm<0,true,true,false><<<dim3(18, 4, 8), 256, SMG>>>(
        p_hff, P[8], P[18], P[9], P[19], p_x1, p_mix, 1024, 256);

    scatter_kernel<<<dim3(NTOK, NB), 256>>>(out);
}